// round 13
// baseline (speedup 1.0000x reference)
#include <cuda_runtime.h>
#include <cuda_bf16.h>

#define N_NODES   1000000
#define D_FEAT    128
#define B_SEGS    1024
#define NWARPS    8
#define NTHREADS  (NWARPS * 32)
#define BLOCKS_PER_SM 3
#define GRID_A    (148 * BLOCKS_PER_SM)     // 444 blocks -> exactly one wave
#define TOT_WARPS (GRID_A * NWARPS)         // 3552
#define ROWS_PW   282                       // ceil(1e6 / 3552)

// Device scratch (no allocations allowed). Zero-initialized at module load;
// the finalize kernel restores g_S/g_W to zero after each use, so every
// graph replay sees zeroed accumulators without a dedicated zeroing launch.
// g_start is fully rewritten by the main kernel each replay.
__device__ __align__(16) float g_e[N_NODES]; // exp(gate) per node
__device__ float g_S[B_SEGS];                // per-segment exp-sum
__device__ float g_W[B_SEGS * D_FEAT];       // per-segment weighted sum
__device__ int   g_start[B_SEGS + 1];        // per-segment start offsets

// Cooperative 4-row warp reduce: 9 shuffles reduce four rows simultaneously.
// On return, lane class (lane&3)==i holds row i's full sum.
__device__ __forceinline__ float coop_reduce4(int lane, float p0, float p1,
                                              float p2, float p3)
{
    float a01 = (lane & 1) ? p1 : p0;
    float b01 = (lane & 1) ? p0 : p1;
    a01 += __shfl_xor_sync(0xffffffffu, b01, 1);
    float a23 = (lane & 1) ? p3 : p2;
    float b23 = (lane & 1) ? p2 : p3;
    a23 += __shfl_xor_sync(0xffffffffu, b23, 1);
    float r = (lane & 2) ? a23 : a01;
    float s = (lane & 2) ? a01 : a23;
    r += __shfl_xor_sync(0xffffffffu, s, 2);
    r += __shfl_xor_sync(0xffffffffu, r, 4);
    r += __shfl_xor_sync(0xffffffffu, r, 8);
    r += __shfl_xor_sync(0xffffffffu, r, 16);
    return r;
}

// ------------------------------------------------------- main fused pass over feat
// Also performs segment-boundary detection inline: every transition index is
// encountered exactly once (in the slow path or a warp prologue), so g_start
// is complete when this kernel finishes.
__global__ __launch_bounds__(NTHREADS, BLOCKS_PER_SM)
void gap_main_kernel(const float* __restrict__ feat,
                     const float* __restrict__ w_gate,
                     const float* __restrict__ b_gate,
                     const int*   __restrict__ seg)
{
    const int tid  = threadIdx.x;
    const int wid  = tid >> 5;
    const int lane = tid & 31;

    const int gw     = blockIdx.x * NWARPS + wid;        // global warp id
    const int wstart = gw * ROWS_PW;
    const int wend   = min(wstart + ROWS_PW, N_NODES);
    if (wstart >= wend) return;

    const float  bg = b_gate[0];
    const float4 w4 = reinterpret_cast<const float4*>(w_gate)[lane];
    const float4* __restrict__ feat4 = reinterpret_cast<const float4*>(feat);

    int    cur  = seg[wstart];                // warp-uniform
    float  Ssum = 0.f;
    float4 acc  = make_float4(0.f, 0.f, 0.f, 0.f);

    // ---- boundary prologue: transitions landing exactly at wstart ----
    if (lane == 0) {
        if (wstart == 0) {
            for (int b = 0; b <= cur; b++) g_start[b] = 0;
        } else {
            const int prev = seg[wstart - 1];
            for (int b = prev + 1; b <= cur; b++) g_start[b] = wstart;
        }
    }

    int n = wstart;
    while (n < wend) {
        if (n + 7 < wend && seg[n] == cur && seg[n + 7] == cur) {
            // ---- 8-row fast path: all loads issued before any reduce (MLP=8) --
            const float4 f0 = __ldg(feat4 + (size_t)(n + 0) * 32 + lane);
            const float4 f1 = __ldg(feat4 + (size_t)(n + 1) * 32 + lane);
            const float4 f2 = __ldg(feat4 + (size_t)(n + 2) * 32 + lane);
            const float4 f3 = __ldg(feat4 + (size_t)(n + 3) * 32 + lane);
            const float4 f4 = __ldg(feat4 + (size_t)(n + 4) * 32 + lane);
            const float4 f5 = __ldg(feat4 + (size_t)(n + 5) * 32 + lane);
            const float4 f6 = __ldg(feat4 + (size_t)(n + 6) * 32 + lane);
            const float4 f7 = __ldg(feat4 + (size_t)(n + 7) * 32 + lane);

            float p0 = f0.x*w4.x + f0.y*w4.y + f0.z*w4.z + f0.w*w4.w;
            float p1 = f1.x*w4.x + f1.y*w4.y + f1.z*w4.z + f1.w*w4.w;
            float p2 = f2.x*w4.x + f2.y*w4.y + f2.z*w4.z + f2.w*w4.w;
            float p3 = f3.x*w4.x + f3.y*w4.y + f3.z*w4.z + f3.w*w4.w;
            float p4 = f4.x*w4.x + f4.y*w4.y + f4.z*w4.z + f4.w*w4.w;
            float p5 = f5.x*w4.x + f5.y*w4.y + f5.z*w4.z + f5.w*w4.w;
            float p6 = f6.x*w4.x + f6.y*w4.y + f6.z*w4.z + f6.w*w4.w;
            float p7 = f7.x*w4.x + f7.y*w4.y + f7.z*w4.z + f7.w*w4.w;

            const float rA = coop_reduce4(lane, p0, p1, p2, p3);
            const float rB = coop_reduce4(lane, p4, p5, p6, p7);

            const float eA = __expf(rA + bg);    // lane class i: row n+i
            const float eB = __expf(rB + bg);    // lane class i: row n+4+i
            if (lane < 4) {
                g_e[n + lane]     = eA;
                g_e[n + 4 + lane] = eB;
            }

            const float e0 = __shfl_sync(0xffffffffu, eA, 0);
            const float e1 = __shfl_sync(0xffffffffu, eA, 1);
            const float e2 = __shfl_sync(0xffffffffu, eA, 2);
            const float e3 = __shfl_sync(0xffffffffu, eA, 3);
            const float e4 = __shfl_sync(0xffffffffu, eB, 0);
            const float e5 = __shfl_sync(0xffffffffu, eB, 1);
            const float e6 = __shfl_sync(0xffffffffu, eB, 2);
            const float e7 = __shfl_sync(0xffffffffu, eB, 3);

            Ssum += ((e0 + e1) + (e2 + e3)) + ((e4 + e5) + (e6 + e7));
            acc.x += e0*f0.x + e1*f1.x + e2*f2.x + e3*f3.x
                   + e4*f4.x + e5*f5.x + e6*f6.x + e7*f7.x;
            acc.y += e0*f0.y + e1*f1.y + e2*f2.y + e3*f3.y
                   + e4*f4.y + e5*f5.y + e6*f6.y + e7*f7.y;
            acc.z += e0*f0.z + e1*f1.z + e2*f2.z + e3*f3.z
                   + e4*f4.z + e5*f5.z + e6*f6.z + e7*f7.z;
            acc.w += e0*f0.w + e1*f1.w + e2*f2.w + e3*f3.w
                   + e4*f4.w + e5*f5.w + e6*f6.w + e7*f7.w;
            n += 8;
        } else if (n + 3 < wend && seg[n] == cur && seg[n + 3] == cur) {
            // ---- 4-row path (near boundaries / tails) ----
            const float4 f0 = __ldg(feat4 + (size_t)(n + 0) * 32 + lane);
            const float4 f1 = __ldg(feat4 + (size_t)(n + 1) * 32 + lane);
            const float4 f2 = __ldg(feat4 + (size_t)(n + 2) * 32 + lane);
            const float4 f3 = __ldg(feat4 + (size_t)(n + 3) * 32 + lane);

            float p0 = f0.x*w4.x + f0.y*w4.y + f0.z*w4.z + f0.w*w4.w;
            float p1 = f1.x*w4.x + f1.y*w4.y + f1.z*w4.z + f1.w*w4.w;
            float p2 = f2.x*w4.x + f2.y*w4.y + f2.z*w4.z + f2.w*w4.w;
            float p3 = f3.x*w4.x + f3.y*w4.y + f3.z*w4.z + f3.w*w4.w;

            const float r = coop_reduce4(lane, p0, p1, p2, p3);
            const float e = __expf(r + bg);
            if (lane < 4) g_e[n + lane] = e;

            const float e0 = __shfl_sync(0xffffffffu, e, 0);
            const float e1 = __shfl_sync(0xffffffffu, e, 1);
            const float e2 = __shfl_sync(0xffffffffu, e, 2);
            const float e3 = __shfl_sync(0xffffffffu, e, 3);

            Ssum += (e0 + e1) + (e2 + e3);
            acc.x += e0*f0.x + e1*f1.x + e2*f2.x + e3*f3.x;
            acc.y += e0*f0.y + e1*f1.y + e2*f2.y + e3*f3.y;
            acc.z += e0*f0.z + e1*f1.z + e2*f2.z + e3*f3.z;
            acc.w += e0*f0.w + e1*f1.w + e2*f2.w + e3*f3.w;
            n += 4;
        } else {
            // ---- slow path: one row, possible segment boundary ----
            const int s = seg[n];
            if (s != cur) {
                // record boundary + flush warp-private partials
                if (lane == 0) {
                    for (int b = cur + 1; b <= s; b++) g_start[b] = n;
                    atomicAdd(&g_S[cur], Ssum);
                }
                float* wp = &g_W[(size_t)cur * D_FEAT + lane * 4];
                atomicAdd(wp + 0, acc.x);
                atomicAdd(wp + 1, acc.y);
                atomicAdd(wp + 2, acc.z);
                atomicAdd(wp + 3, acc.w);
                cur = s; Ssum = 0.f; acc = make_float4(0.f, 0.f, 0.f, 0.f);
            }
            const float4 f = __ldg(feat4 + (size_t)n * 32 + lane);
            float p = f.x*w4.x + f.y*w4.y + f.z*w4.z + f.w*w4.w;
            #pragma unroll
            for (int sh = 16; sh >= 1; sh >>= 1)
                p += __shfl_xor_sync(0xffffffffu, p, sh);
            const float e = __expf(p + bg);
            if (lane == 0) g_e[n] = e;
            Ssum += e;
            acc.x += e*f.x; acc.y += e*f.y; acc.z += e*f.z; acc.w += e*f.w;
            n += 1;
        }
    }

    // ---- final flush + boundary epilogue ----
    if (lane == 0) {
        atomicAdd(&g_S[cur], Ssum);
        if (wend == N_NODES)
            for (int b = cur + 1; b <= B_SEGS; b++) g_start[b] = N_NODES;
    }
    float* wp = &g_W[(size_t)cur * D_FEAT + lane * 4];
    atomicAdd(wp + 0, acc.x);
    atomicAdd(wp + 1, acc.y);
    atomicAdd(wp + 2, acc.z);
    atomicAdd(wp + 3, acc.w);
}

// ---------------- finalize + alpha, one block per segment -------------------
// Flat loads of precomputed bounds, block-uniform invS, vectorized alpha body,
// and zero-restore of the accumulators for the next replay.
__global__ __launch_bounds__(256)
void gap_finalize_alpha_kernel(float* __restrict__ readout,
                               float* __restrict__ alpha)
{
    const int b   = blockIdx.x;
    const int tid = threadIdx.x;

    const int start = g_start[b];
    const int end   = g_start[b + 1];
    const float S   = g_S[b];
    const float invS = (S > 0.f) ? (1.0f / S) : 0.0f;

    if (tid < D_FEAT) {
        const size_t idx = (size_t)b * D_FEAT + tid;
        readout[idx] = g_W[idx] * invS;
        g_W[idx] = 0.f;                         // restore zeros for next replay
    }
    if (tid == 0) g_S[b] = 0.f;

    // alpha: scalar head/tail, float4 body (g_e and alpha are 16B-aligned).
    const int a4 = (start + 3) & ~3;
    const int e4 = end & ~3;
    for (int n = start + tid; n < min(a4, end); n += 256)
        alpha[n] = g_e[n] * invS;
    if (a4 < e4) {
        const float4* e4p = reinterpret_cast<const float4*>(g_e);
        float4*       a4p = reinterpret_cast<float4*>(alpha);
        for (int q = (a4 >> 2) + tid; q < (e4 >> 2); q += 256) {
            const float4 v = e4p[q];
            float4 a;
            a.x = v.x * invS; a.y = v.y * invS; a.z = v.z * invS; a.w = v.w * invS;
            a4p[q] = a;
        }
    }
    for (int n = max(e4, a4) + tid; n < end; n += 256)
        alpha[n] = g_e[n] * invS;
}

extern "C" void kernel_launch(void* const* d_in, const int* in_sizes, int n_in,
                              void* d_out, int out_size)
{
    const float* feat   = (const float*)d_in[0];
    const float* w_gate = (const float*)d_in[1];
    const float* b_gate = (const float*)d_in[2];
    const int*   seg    = (const int*)d_in[3];

    float* out     = (float*)d_out;
    float* readout = out;                            // [B, D]
    float* alpha   = out + (size_t)B_SEGS * D_FEAT;  // [N, 1]

    gap_main_kernel<<<GRID_A, NTHREADS>>>(feat, w_gate, b_gate, seg);
    gap_finalize_alpha_kernel<<<B_SEGS, 256>>>(readout, alpha);
}

// round 14
// speedup vs baseline: 1.0047x; 1.0047x over previous
#include <cuda_runtime.h>
#include <cuda_bf16.h>

#define N_NODES   1000000
#define D_FEAT    128
#define B_SEGS    1024
#define NWARPS    8
#define NTHREADS  (NWARPS * 32)
#define BLOCKS_PER_SM 5
#define GRID_A    (148 * BLOCKS_PER_SM)     // 740 blocks -> exactly one wave
#define TOT_WARPS (GRID_A * NWARPS)         // 5920
#define ROWS_PW   169                       // ceil(1e6 / 5920)

#define GRID_F    (148 * 4)                 // finalize: flat, all co-resident
#define NQ_RD     ((B_SEGS * D_FEAT) / 4)   // 32768 readout quads
#define NQ_AL     (N_NODES / 4)             // 250000 alpha quads

// Device scratch (no allocations allowed). Zero-initialized at module load.
// The finalize kernel restores g_S/g_W and its counter to zero before
// finishing, so every graph replay sees identical initial state.
__device__ __align__(16) float g_e[N_NODES]; // exp(gate) per node
__device__ float g_S[B_SEGS];                // per-segment exp-sum
__device__ __align__(16) float g_W[B_SEGS * D_FEAT]; // per-segment weighted sum
__device__ unsigned g_done;                  // finalize exit counter

// Cooperative 4-row warp reduce: 9 shuffles reduce four rows simultaneously.
// On return, lane class (lane&3)==i holds row i's full sum.
__device__ __forceinline__ float coop_reduce4(int lane, float p0, float p1,
                                              float p2, float p3)
{
    float a01 = (lane & 1) ? p1 : p0;
    float b01 = (lane & 1) ? p0 : p1;
    a01 += __shfl_xor_sync(0xffffffffu, b01, 1);
    float a23 = (lane & 1) ? p3 : p2;
    float b23 = (lane & 1) ? p2 : p3;
    a23 += __shfl_xor_sync(0xffffffffu, b23, 1);
    float r = (lane & 2) ? a23 : a01;
    float s = (lane & 2) ? a01 : a23;
    r += __shfl_xor_sync(0xffffffffu, s, 2);
    r += __shfl_xor_sync(0xffffffffu, r, 4);
    r += __shfl_xor_sync(0xffffffffu, r, 8);
    r += __shfl_xor_sync(0xffffffffu, r, 16);
    return r;
}

// ------------------------------------------------------- main fused pass over feat
__global__ __launch_bounds__(NTHREADS, BLOCKS_PER_SM)
void gap_main_kernel(const float* __restrict__ feat,
                     const float* __restrict__ w_gate,
                     const float* __restrict__ b_gate,
                     const int*   __restrict__ seg)
{
    const int tid  = threadIdx.x;
    const int wid  = tid >> 5;
    const int lane = tid & 31;

    const int gw     = blockIdx.x * NWARPS + wid;        // global warp id
    const int wstart = gw * ROWS_PW;
    const int wend   = min(wstart + ROWS_PW, N_NODES);
    if (wstart >= wend) return;

    const float  bg = b_gate[0];
    const float4 w4 = reinterpret_cast<const float4*>(w_gate)[lane];
    const float4* __restrict__ feat4 = reinterpret_cast<const float4*>(feat);

    int    cur  = seg[wstart];                // warp-uniform
    float  Ssum = 0.f;
    float4 acc  = make_float4(0.f, 0.f, 0.f, 0.f);

    int n = wstart;
    while (n < wend) {
        if (n + 3 < wend && seg[n] == cur && seg[n + 3] == cur) {
            // ---- fast path: 4 rows, same segment (sorted => all 4 equal) ----
            const float4 f0 = __ldg(feat4 + (size_t)(n + 0) * 32 + lane);
            const float4 f1 = __ldg(feat4 + (size_t)(n + 1) * 32 + lane);
            const float4 f2 = __ldg(feat4 + (size_t)(n + 2) * 32 + lane);
            const float4 f3 = __ldg(feat4 + (size_t)(n + 3) * 32 + lane);

            float p0 = f0.x*w4.x + f0.y*w4.y + f0.z*w4.z + f0.w*w4.w;
            float p1 = f1.x*w4.x + f1.y*w4.y + f1.z*w4.z + f1.w*w4.w;
            float p2 = f2.x*w4.x + f2.y*w4.y + f2.z*w4.z + f2.w*w4.w;
            float p3 = f3.x*w4.x + f3.y*w4.y + f3.z*w4.z + f3.w*w4.w;

            const float r = coop_reduce4(lane, p0, p1, p2, p3);

            // One expf per lane (its class's row), instead of four.
            const float e = __expf(r + bg);
            if (lane < 4) g_e[n + lane] = e;     // lane i holds row i's e

            const float e0 = __shfl_sync(0xffffffffu, e, 0);
            const float e1 = __shfl_sync(0xffffffffu, e, 1);
            const float e2 = __shfl_sync(0xffffffffu, e, 2);
            const float e3 = __shfl_sync(0xffffffffu, e, 3);

            Ssum += (e0 + e1) + (e2 + e3);
            acc.x += e0*f0.x + e1*f1.x + e2*f2.x + e3*f3.x;
            acc.y += e0*f0.y + e1*f1.y + e2*f2.y + e3*f3.y;
            acc.z += e0*f0.z + e1*f1.z + e2*f2.z + e3*f3.z;
            acc.w += e0*f0.w + e1*f1.w + e2*f2.w + e3*f3.w;
            n += 4;
        } else {
            // ---- slow path: one row, possible segment boundary ----
            const int s = seg[n];
            if (s != cur) {
                // flush warp-private partials for finished segment
                if (lane == 0) atomicAdd(&g_S[cur], Ssum);
                float* wp = &g_W[(size_t)cur * D_FEAT + lane * 4];
                atomicAdd(wp + 0, acc.x);
                atomicAdd(wp + 1, acc.y);
                atomicAdd(wp + 2, acc.z);
                atomicAdd(wp + 3, acc.w);
                cur = s; Ssum = 0.f; acc = make_float4(0.f, 0.f, 0.f, 0.f);
            }
            const float4 f = __ldg(feat4 + (size_t)n * 32 + lane);
            float p = f.x*w4.x + f.y*w4.y + f.z*w4.z + f.w*w4.w;
            #pragma unroll
            for (int sh = 16; sh >= 1; sh >>= 1)
                p += __shfl_xor_sync(0xffffffffu, p, sh);
            const float e = __expf(p + bg);
            if (lane == 0) g_e[n] = e;
            Ssum += e;
            acc.x += e*f.x; acc.y += e*f.y; acc.z += e*f.z; acc.w += e*f.w;
            n += 1;
        }
    }
    // final flush
    if (lane == 0) atomicAdd(&g_S[cur], Ssum);
    float* wp = &g_W[(size_t)cur * D_FEAT + lane * 4];
    atomicAdd(wp + 0, acc.x);
    atomicAdd(wp + 1, acc.y);
    atomicAdd(wp + 2, acc.z);
    atomicAdd(wp + 3, acc.w);
}

// ---------------- finalize: flat gtid-partitioned readout + alpha -----------
// No per-segment blocks, no dependent bound chains. g_S (4 KB) stays hot in
// L1/L2 for the alpha gather. The last block to finish zeroes g_S and resets
// the counter (no other block waits), restoring initial state for the next
// graph replay.
__global__ __launch_bounds__(256)
void gap_finalize_kernel(const int* __restrict__ seg,
                         float* __restrict__ readout,
                         float* __restrict__ alpha)
{
    const int tid  = threadIdx.x;
    const int gtid = blockIdx.x * 256 + tid;
    const int gstr = GRID_F * 256;

    // ---- readout: b = quad >> 5 (32 quads per segment row) ----
    {
        float4* w4p = reinterpret_cast<float4*>(g_W);
        float4* r4p = reinterpret_cast<float4*>(readout);
        for (int q = gtid; q < NQ_RD; q += gstr) {
            const int   b    = q >> 5;
            const float S    = g_S[b];
            const float invS = (S > 0.f) ? (1.0f / S) : 0.0f;
            float4 w = w4p[q];
            float4 r;
            r.x = w.x * invS; r.y = w.y * invS; r.z = w.z * invS; r.w = w.w * invS;
            r4p[q] = r;
            w4p[q] = make_float4(0.f, 0.f, 0.f, 0.f);   // restore zeros
        }
    }

    // ---- alpha: independent load pairs + hot g_S gather ----
    {
        const float4* e4p = reinterpret_cast<const float4*>(g_e);
        const int4*   s4p = reinterpret_cast<const int4*>(seg);
        float4*       a4p = reinterpret_cast<float4*>(alpha);
        for (int q = gtid; q < NQ_AL; q += gstr) {
            const float4 e = e4p[q];
            const int4   s = s4p[q];
            float4 a;
            a.x = __fdividef(e.x, g_S[s.x]);
            a.y = __fdividef(e.y, g_S[s.y]);
            a.z = __fdividef(e.z, g_S[s.z]);
            a.w = __fdividef(e.w, g_S[s.w]);
            a4p[q] = a;
        }
    }

    // ---- last-block-out: zero g_S + reset counter (no waiting) ----
    __shared__ int s_last;
    __syncthreads();
    if (tid == 0) {
        __threadfence();                       // order this block's g_S reads
        const unsigned old = atomicAdd(&g_done, 1);
        s_last = (old == GRID_F - 1);
    }
    __syncthreads();
    if (s_last) {
        for (int b = tid; b < B_SEGS; b += 256) g_S[b] = 0.f;
        __syncthreads();
        if (tid == 0) {
            __threadfence();
            g_done = 0u;                       // restore counter for next replay
            __threadfence();
        }
    }
}

extern "C" void kernel_launch(void* const* d_in, const int* in_sizes, int n_in,
                              void* d_out, int out_size)
{
    const float* feat   = (const float*)d_in[0];
    const float* w_gate = (const float*)d_in[1];
    const float* b_gate = (const float*)d_in[2];
    const int*   seg    = (const int*)d_in[3];

    float* out     = (float*)d_out;
    float* readout = out;                            // [B, D]
    float* alpha   = out + (size_t)B_SEGS * D_FEAT;  // [N, 1]

    gap_main_kernel<<<GRID_A, NTHREADS>>>(feat, w_gate, b_gate, seg);
    gap_finalize_kernel<<<GRID_F, 256>>>(seg, readout, alpha);
}

// round 15
// speedup vs baseline: 1.0274x; 1.0225x over previous
#include <cuda_runtime.h>
#include <cuda_bf16.h>

#define N_NODES   1000000
#define D_FEAT    128
#define B_SEGS    1024
#define NWARPS    8
#define NTHREADS  (NWARPS * 32)
#define BLOCKS_PER_SM 5
#define GRID_A    (148 * BLOCKS_PER_SM)     // 740 blocks -> exactly one wave
#define TOT_WARPS (GRID_A * NWARPS)         // 5920
#define ROWS_PW   169                       // ceil(1e6 / 5920)

// Device scratch (no allocations allowed). Zero-initialized at module load;
// the finalize kernel restores g_S/g_W to zero after each use, so every
// graph replay sees zeroed accumulators without a dedicated zeroing launch.
// g_start is fully rewritten by the main kernel each replay.
__device__ __align__(16) float g_e[N_NODES]; // exp(gate) per node
__device__ float g_S[B_SEGS];                // per-segment exp-sum
__device__ float g_W[B_SEGS * D_FEAT];       // per-segment weighted sum
__device__ int   g_start[B_SEGS + 1];        // per-segment start offsets

// Cooperative 4-row warp reduce: 9 shuffles reduce four rows simultaneously.
// On return, lane class (lane&3)==i holds row i's full sum.
__device__ __forceinline__ float coop_reduce4(int lane, float p0, float p1,
                                              float p2, float p3)
{
    float a01 = (lane & 1) ? p1 : p0;
    float b01 = (lane & 1) ? p0 : p1;
    a01 += __shfl_xor_sync(0xffffffffu, b01, 1);
    float a23 = (lane & 1) ? p3 : p2;
    float b23 = (lane & 1) ? p2 : p3;
    a23 += __shfl_xor_sync(0xffffffffu, b23, 1);
    float r = (lane & 2) ? a23 : a01;
    float s = (lane & 2) ? a01 : a23;
    r += __shfl_xor_sync(0xffffffffu, s, 2);
    r += __shfl_xor_sync(0xffffffffu, r, 4);
    r += __shfl_xor_sync(0xffffffffu, r, 8);
    r += __shfl_xor_sync(0xffffffffu, r, 16);
    return r;
}

// ------------------------------------------------------- main fused pass over feat
// Also performs segment-boundary detection inline. Signals PDL dependents
// after the final flush so the finalize grid can pre-launch into the tail.
__global__ __launch_bounds__(NTHREADS, BLOCKS_PER_SM)
void gap_main_kernel(const float* __restrict__ feat,
                     const float* __restrict__ w_gate,
                     const float* __restrict__ b_gate,
                     const int*   __restrict__ seg)
{
    const int tid  = threadIdx.x;
    const int wid  = tid >> 5;
    const int lane = tid & 31;

    const int gw     = blockIdx.x * NWARPS + wid;        // global warp id
    const int wstart = gw * ROWS_PW;
    const int wend   = min(wstart + ROWS_PW, N_NODES);

    if (wstart < wend) {
        const float  bg = b_gate[0];
        const float4 w4 = reinterpret_cast<const float4*>(w_gate)[lane];
        const float4* __restrict__ feat4 = reinterpret_cast<const float4*>(feat);

        int    cur  = seg[wstart];                // warp-uniform
        float  Ssum = 0.f;
        float4 acc  = make_float4(0.f, 0.f, 0.f, 0.f);

        // ---- boundary prologue: transitions landing exactly at wstart ----
        if (lane == 0) {
            if (wstart == 0) {
                for (int b = 0; b <= cur; b++) g_start[b] = 0;
            } else {
                const int prev = seg[wstart - 1];
                for (int b = prev + 1; b <= cur; b++) g_start[b] = wstart;
            }
        }

        int n = wstart;
        while (n < wend) {
            if (n + 3 < wend && seg[n] == cur && seg[n + 3] == cur) {
                // ---- fast path: 4 rows, same segment ----
                const float4 f0 = __ldg(feat4 + (size_t)(n + 0) * 32 + lane);
                const float4 f1 = __ldg(feat4 + (size_t)(n + 1) * 32 + lane);
                const float4 f2 = __ldg(feat4 + (size_t)(n + 2) * 32 + lane);
                const float4 f3 = __ldg(feat4 + (size_t)(n + 3) * 32 + lane);

                float p0 = f0.x*w4.x + f0.y*w4.y + f0.z*w4.z + f0.w*w4.w;
                float p1 = f1.x*w4.x + f1.y*w4.y + f1.z*w4.z + f1.w*w4.w;
                float p2 = f2.x*w4.x + f2.y*w4.y + f2.z*w4.z + f2.w*w4.w;
                float p3 = f3.x*w4.x + f3.y*w4.y + f3.z*w4.z + f3.w*w4.w;

                const float r = coop_reduce4(lane, p0, p1, p2, p3);

                // One expf per lane (its class's row), instead of four.
                const float e = __expf(r + bg);
                if (lane < 4) g_e[n + lane] = e;     // lane i holds row i's e

                const float e0 = __shfl_sync(0xffffffffu, e, 0);
                const float e1 = __shfl_sync(0xffffffffu, e, 1);
                const float e2 = __shfl_sync(0xffffffffu, e, 2);
                const float e3 = __shfl_sync(0xffffffffu, e, 3);

                Ssum += (e0 + e1) + (e2 + e3);
                acc.x += e0*f0.x + e1*f1.x + e2*f2.x + e3*f3.x;
                acc.y += e0*f0.y + e1*f1.y + e2*f2.y + e3*f3.y;
                acc.z += e0*f0.z + e1*f1.z + e2*f2.z + e3*f3.z;
                acc.w += e0*f0.w + e1*f1.w + e2*f2.w + e3*f3.w;
                n += 4;
            } else {
                // ---- slow path: one row, possible segment boundary ----
                const int s = seg[n];
                if (s != cur) {
                    // record boundary + flush warp-private partials
                    if (lane == 0) {
                        for (int b = cur + 1; b <= s; b++) g_start[b] = n;
                        atomicAdd(&g_S[cur], Ssum);
                    }
                    float* wp = &g_W[(size_t)cur * D_FEAT + lane * 4];
                    atomicAdd(wp + 0, acc.x);
                    atomicAdd(wp + 1, acc.y);
                    atomicAdd(wp + 2, acc.z);
                    atomicAdd(wp + 3, acc.w);
                    cur = s; Ssum = 0.f; acc = make_float4(0.f, 0.f, 0.f, 0.f);
                }
                const float4 f = __ldg(feat4 + (size_t)n * 32 + lane);
                float p = f.x*w4.x + f.y*w4.y + f.z*w4.z + f.w*w4.w;
                #pragma unroll
                for (int sh = 16; sh >= 1; sh >>= 1)
                    p += __shfl_xor_sync(0xffffffffu, p, sh);
                const float e = __expf(p + bg);
                if (lane == 0) g_e[n] = e;
                Ssum += e;
                acc.x += e*f.x; acc.y += e*f.y; acc.z += e*f.z; acc.w += e*f.w;
                n += 1;
            }
        }

        // ---- final flush + boundary epilogue ----
        if (lane == 0) {
            atomicAdd(&g_S[cur], Ssum);
            if (wend == N_NODES)
                for (int b = cur + 1; b <= B_SEGS; b++) g_start[b] = N_NODES;
        }
        float* wp = &g_W[(size_t)cur * D_FEAT + lane * 4];
        atomicAdd(wp + 0, acc.x);
        atomicAdd(wp + 1, acc.y);
        atomicAdd(wp + 2, acc.z);
        atomicAdd(wp + 3, acc.w);
    }

    // PDL: allow the dependent finalize grid to launch; all this block's
    // writes above are visible to dependents after their griddepcontrol.wait.
    asm volatile("griddepcontrol.launch_dependents;" ::: "memory");
}

// ---------------- finalize + alpha, one block per segment -------------------
// PDL-prelaunched: blocks get scheduled during the main kernel's tail, wait
// for the dependency, then run with warm scheduling state.
__global__ __launch_bounds__(256)
void gap_finalize_alpha_kernel(float* __restrict__ readout,
                               float* __restrict__ alpha)
{
    // Wait until the primary grid's writes (g_S/g_W/g_e/g_start) are visible.
    asm volatile("griddepcontrol.wait;" ::: "memory");

    const int b   = blockIdx.x;
    const int tid = threadIdx.x;

    const int start = g_start[b];
    const int end   = g_start[b + 1];
    const float S   = g_S[b];
    const float invS = (S > 0.f) ? (1.0f / S) : 0.0f;

    if (tid < D_FEAT) {
        const size_t idx = (size_t)b * D_FEAT + tid;
        readout[idx] = g_W[idx] * invS;
        g_W[idx] = 0.f;                         // restore zeros for next replay
    }
    if (tid == 0) g_S[b] = 0.f;

    // alpha: scalar head/tail, float4 body (g_e and alpha are 16B-aligned).
    const int a4 = (start + 3) & ~3;
    const int e4 = end & ~3;
    for (int n = start + tid; n < min(a4, end); n += 256)
        alpha[n] = g_e[n] * invS;
    if (a4 < e4) {
        const float4* e4p = reinterpret_cast<const float4*>(g_e);
        float4*       a4p = reinterpret_cast<float4*>(alpha);
        for (int q = (a4 >> 2) + tid; q < (e4 >> 2); q += 256) {
            const float4 v = e4p[q];
            float4 a;
            a.x = v.x * invS; a.y = v.y * invS; a.z = v.z * invS; a.w = v.w * invS;
            a4p[q] = a;
        }
    }
    for (int n = max(e4, a4) + tid; n < end; n += 256)
        alpha[n] = g_e[n] * invS;
}

extern "C" void kernel_launch(void* const* d_in, const int* in_sizes, int n_in,
                              void* d_out, int out_size)
{
    const float* feat   = (const float*)d_in[0];
    const float* w_gate = (const float*)d_in[1];
    const float* b_gate = (const float*)d_in[2];
    const int*   seg    = (const int*)d_in[3];

    float* out     = (float*)d_out;
    float* readout = out;                            // [B, D]
    float* alpha   = out + (size_t)B_SEGS * D_FEAT;  // [N, 1]

    gap_main_kernel<<<GRID_A, NTHREADS>>>(feat, w_gate, b_gate, seg);

    // Finalize with Programmatic Dependent Launch: overlaps its launch and
    // block-scheduling ramp with the main kernel's tail.
    cudaLaunchConfig_t cfg = {};
    cfg.gridDim  = dim3(B_SEGS, 1, 1);
    cfg.blockDim = dim3(256, 1, 1);
    cfg.dynamicSmemBytes = 0;
    cfg.stream = 0;
    cudaLaunchAttribute attr[1];
    attr[0].id = cudaLaunchAttributeProgrammaticStreamSerialization;
    attr[0].val.programmaticStreamSerializationAllowed = 1;
    cfg.attrs = attr;
    cfg.numAttrs = 1;
    cudaLaunchKernelEx(&cfg, gap_finalize_alpha_kernel, readout, alpha);
}

// round 16
// speedup vs baseline: 1.0480x; 1.0201x over previous
#include <cuda_runtime.h>
#include <cuda_bf16.h>

#define N_NODES   1000000
#define D_FEAT    128
#define B_SEGS    1024
#define NWARPS    8
#define NTHREADS  (NWARPS * 32)
#define BLOCKS_PER_SM 4
#define GRID_A    (148 * BLOCKS_PER_SM)     // 592 blocks -> exactly one wave
#define TOT_WARPS (GRID_A * NWARPS)         // 4736
#define ROWS_PW   212                       // ceil(1e6 / 4736)

// Device scratch (no allocations allowed). Zero-initialized at module load;
// the finalize kernel restores g_S/g_W to zero after each use, so every
// graph replay sees zeroed accumulators without a dedicated zeroing launch.
// g_start is fully rewritten by the main kernel each replay.
__device__ __align__(16) float g_e[N_NODES]; // exp(gate) per node
__device__ float g_S[B_SEGS];                // per-segment exp-sum
__device__ float g_W[B_SEGS * D_FEAT];       // per-segment weighted sum
__device__ int   g_start[B_SEGS + 1];        // per-segment start offsets

// Cooperative 4-row warp reduce: 9 shuffles reduce four rows simultaneously.
// On return, lane class (lane&3)==i holds row i's full sum.
__device__ __forceinline__ float coop_reduce4(int lane, float p0, float p1,
                                              float p2, float p3)
{
    float a01 = (lane & 1) ? p1 : p0;
    float b01 = (lane & 1) ? p0 : p1;
    a01 += __shfl_xor_sync(0xffffffffu, b01, 1);
    float a23 = (lane & 1) ? p3 : p2;
    float b23 = (lane & 1) ? p2 : p3;
    a23 += __shfl_xor_sync(0xffffffffu, b23, 1);
    float r = (lane & 2) ? a23 : a01;
    float s = (lane & 2) ? a01 : a23;
    r += __shfl_xor_sync(0xffffffffu, s, 2);
    r += __shfl_xor_sync(0xffffffffu, r, 4);
    r += __shfl_xor_sync(0xffffffffu, r, 8);
    r += __shfl_xor_sync(0xffffffffu, r, 16);
    return r;
}

// Cooperative 2-row warp reduce: 5 shuffles. On return, lane class (lane&1)==i
// holds row i's full sum.
__device__ __forceinline__ float coop_reduce2(int lane, float p0, float p1)
{
    float a = (lane & 1) ? p1 : p0;
    float b = (lane & 1) ? p0 : p1;
    a += __shfl_xor_sync(0xffffffffu, b, 1);
    a += __shfl_xor_sync(0xffffffffu, a, 2);
    a += __shfl_xor_sync(0xffffffffu, a, 4);
    a += __shfl_xor_sync(0xffffffffu, a, 8);
    a += __shfl_xor_sync(0xffffffffu, a, 16);
    return a;
}

// ------------------------------------------------------- main fused pass over feat
// Also performs segment-boundary detection inline: every transition index is
// encountered exactly once (in the slow path or a warp prologue), so g_start
// is complete when this kernel finishes.
__global__ __launch_bounds__(NTHREADS, BLOCKS_PER_SM)
void gap_main_kernel(const float* __restrict__ feat,
                     const float* __restrict__ w_gate,
                     const float* __restrict__ b_gate,
                     const int*   __restrict__ seg)
{
    const int tid  = threadIdx.x;
    const int wid  = tid >> 5;
    const int lane = tid & 31;

    const int gw     = blockIdx.x * NWARPS + wid;        // global warp id
    const int wstart = gw * ROWS_PW;
    const int wend   = min(wstart + ROWS_PW, N_NODES);
    if (wstart >= wend) return;

    const float  bg = b_gate[0];
    const float4 w4 = reinterpret_cast<const float4*>(w_gate)[lane];
    const float4* __restrict__ feat4 = reinterpret_cast<const float4*>(feat);

    int    cur  = seg[wstart];                // warp-uniform
    float  Ssum = 0.f;
    float4 acc  = make_float4(0.f, 0.f, 0.f, 0.f);

    // ---- boundary prologue: transitions landing exactly at wstart ----
    if (lane == 0) {
        if (wstart == 0) {
            for (int b = 0; b <= cur; b++) g_start[b] = 0;
        } else {
            const int prev = seg[wstart - 1];
            for (int b = prev + 1; b <= cur; b++) g_start[b] = wstart;
        }
    }

    int n = wstart;
    while (n < wend) {
        if (n + 5 < wend && seg[n] == cur && seg[n + 5] == cur) {
            // ---- 6-row fast path: all loads issued before any reduce (MLP=6) --
            const float4 f0 = __ldg(feat4 + (size_t)(n + 0) * 32 + lane);
            const float4 f1 = __ldg(feat4 + (size_t)(n + 1) * 32 + lane);
            const float4 f2 = __ldg(feat4 + (size_t)(n + 2) * 32 + lane);
            const float4 f3 = __ldg(feat4 + (size_t)(n + 3) * 32 + lane);
            const float4 f4 = __ldg(feat4 + (size_t)(n + 4) * 32 + lane);
            const float4 f5 = __ldg(feat4 + (size_t)(n + 5) * 32 + lane);

            float p0 = f0.x*w4.x + f0.y*w4.y + f0.z*w4.z + f0.w*w4.w;
            float p1 = f1.x*w4.x + f1.y*w4.y + f1.z*w4.z + f1.w*w4.w;
            float p2 = f2.x*w4.x + f2.y*w4.y + f2.z*w4.z + f2.w*w4.w;
            float p3 = f3.x*w4.x + f3.y*w4.y + f3.z*w4.z + f3.w*w4.w;
            float p4 = f4.x*w4.x + f4.y*w4.y + f4.z*w4.z + f4.w*w4.w;
            float p5 = f5.x*w4.x + f5.y*w4.y + f5.z*w4.z + f5.w*w4.w;

            const float rA = coop_reduce4(lane, p0, p1, p2, p3);
            const float rB = coop_reduce2(lane, p4, p5);

            const float eA = __expf(rA + bg);    // lane class (lane&3): row n+i
            const float eB = __expf(rB + bg);    // lane class (lane&1): row n+4+i
            if (lane < 4) g_e[n + lane] = eA;
            if (lane < 2) g_e[n + 4 + lane] = eB;

            const float e0 = __shfl_sync(0xffffffffu, eA, 0);
            const float e1 = __shfl_sync(0xffffffffu, eA, 1);
            const float e2 = __shfl_sync(0xffffffffu, eA, 2);
            const float e3 = __shfl_sync(0xffffffffu, eA, 3);
            const float e4 = __shfl_sync(0xffffffffu, eB, 0);
            const float e5 = __shfl_sync(0xffffffffu, eB, 1);

            Ssum += ((e0 + e1) + (e2 + e3)) + (e4 + e5);
            acc.x += e0*f0.x + e1*f1.x + e2*f2.x + e3*f3.x + e4*f4.x + e5*f5.x;
            acc.y += e0*f0.y + e1*f1.y + e2*f2.y + e3*f3.y + e4*f4.y + e5*f5.y;
            acc.z += e0*f0.z + e1*f1.z + e2*f2.z + e3*f3.z + e4*f4.z + e5*f5.z;
            acc.w += e0*f0.w + e1*f1.w + e2*f2.w + e3*f3.w + e4*f4.w + e5*f5.w;
            n += 6;
        } else if (n + 3 < wend && seg[n] == cur && seg[n + 3] == cur) {
            // ---- 4-row path (near boundaries / tails) ----
            const float4 f0 = __ldg(feat4 + (size_t)(n + 0) * 32 + lane);
            const float4 f1 = __ldg(feat4 + (size_t)(n + 1) * 32 + lane);
            const float4 f2 = __ldg(feat4 + (size_t)(n + 2) * 32 + lane);
            const float4 f3 = __ldg(feat4 + (size_t)(n + 3) * 32 + lane);

            float p0 = f0.x*w4.x + f0.y*w4.y + f0.z*w4.z + f0.w*w4.w;
            float p1 = f1.x*w4.x + f1.y*w4.y + f1.z*w4.z + f1.w*w4.w;
            float p2 = f2.x*w4.x + f2.y*w4.y + f2.z*w4.z + f2.w*w4.w;
            float p3 = f3.x*w4.x + f3.y*w4.y + f3.z*w4.z + f3.w*w4.w;

            const float r = coop_reduce4(lane, p0, p1, p2, p3);
            const float e = __expf(r + bg);
            if (lane < 4) g_e[n + lane] = e;

            const float e0 = __shfl_sync(0xffffffffu, e, 0);
            const float e1 = __shfl_sync(0xffffffffu, e, 1);
            const float e2 = __shfl_sync(0xffffffffu, e, 2);
            const float e3 = __shfl_sync(0xffffffffu, e, 3);

            Ssum += (e0 + e1) + (e2 + e3);
            acc.x += e0*f0.x + e1*f1.x + e2*f2.x + e3*f3.x;
            acc.y += e0*f0.y + e1*f1.y + e2*f2.y + e3*f3.y;
            acc.z += e0*f0.z + e1*f1.z + e2*f2.z + e3*f3.z;
            acc.w += e0*f0.w + e1*f1.w + e2*f2.w + e3*f3.w;
            n += 4;
        } else {
            // ---- slow path: one row, possible segment boundary ----
            const int s = seg[n];
            if (s != cur) {
                // record boundary + flush warp-private partials
                if (lane == 0) {
                    for (int b = cur + 1; b <= s; b++) g_start[b] = n;
                    atomicAdd(&g_S[cur], Ssum);
                }
                float* wp = &g_W[(size_t)cur * D_FEAT + lane * 4];
                atomicAdd(wp + 0, acc.x);
                atomicAdd(wp + 1, acc.y);
                atomicAdd(wp + 2, acc.z);
                atomicAdd(wp + 3, acc.w);
                cur = s; Ssum = 0.f; acc = make_float4(0.f, 0.f, 0.f, 0.f);
            }
            const float4 f = __ldg(feat4 + (size_t)n * 32 + lane);
            float p = f.x*w4.x + f.y*w4.y + f.z*w4.z + f.w*w4.w;
            #pragma unroll
            for (int sh = 16; sh >= 1; sh >>= 1)
                p += __shfl_xor_sync(0xffffffffu, p, sh);
            const float e = __expf(p + bg);
            if (lane == 0) g_e[n] = e;
            Ssum += e;
            acc.x += e*f.x; acc.y += e*f.y; acc.z += e*f.z; acc.w += e*f.w;
            n += 1;
        }
    }

    // ---- final flush + boundary epilogue ----
    if (lane == 0) {
        atomicAdd(&g_S[cur], Ssum);
        if (wend == N_NODES)
            for (int b = cur + 1; b <= B_SEGS; b++) g_start[b] = N_NODES;
    }
    float* wp = &g_W[(size_t)cur * D_FEAT + lane * 4];
    atomicAdd(wp + 0, acc.x);
    atomicAdd(wp + 1, acc.y);
    atomicAdd(wp + 2, acc.z);
    atomicAdd(wp + 3, acc.w);
}

// ---------------- finalize + alpha, one block per segment -------------------
// Flat loads of precomputed bounds, block-uniform invS, vectorized alpha body,
// and zero-restore of the accumulators for the next replay.
__global__ __launch_bounds__(256)
void gap_finalize_alpha_kernel(float* __restrict__ readout,
                               float* __restrict__ alpha)
{
    const int b   = blockIdx.x;
    const int tid = threadIdx.x;

    const int start = g_start[b];
    const int end   = g_start[b + 1];
    const float S   = g_S[b];
    const float invS = (S > 0.f) ? (1.0f / S) : 0.0f;

    if (tid < D_FEAT) {
        const size_t idx = (size_t)b * D_FEAT + tid;
        readout[idx] = g_W[idx] * invS;
        g_W[idx] = 0.f;                         // restore zeros for next replay
    }
    if (tid == 0) g_S[b] = 0.f;

    // alpha: scalar head/tail, float4 body (g_e and alpha are 16B-aligned).
    const int a4 = (start + 3) & ~3;
    const int e4 = end & ~3;
    for (int n = start + tid; n < min(a4, end); n += 256)
        alpha[n] = g_e[n] * invS;
    if (a4 < e4) {
        const float4* e4p = reinterpret_cast<const float4*>(g_e);
        float4*       a4p = reinterpret_cast<float4*>(alpha);
        for (int q = (a4 >> 2) + tid; q < (e4 >> 2); q += 256) {
            const float4 v = e4p[q];
            float4 a;
            a.x = v.x * invS; a.y = v.y * invS; a.z = v.z * invS; a.w = v.w * invS;
            a4p[q] = a;
        }
    }
    for (int n = max(e4, a4) + tid; n < end; n += 256)
        alpha[n] = g_e[n] * invS;
}

extern "C" void kernel_launch(void* const* d_in, const int* in_sizes, int n_in,
                              void* d_out, int out_size)
{
    const float* feat   = (const float*)d_in[0];
    const float* w_gate = (const float*)d_in[1];
    const float* b_gate = (const float*)d_in[2];
    const int*   seg    = (const int*)d_in[3];

    float* out     = (float*)d_out;
    float* readout = out;                            // [B, D]
    float* alpha   = out + (size_t)B_SEGS * D_FEAT;  // [N, 1]

    gap_main_kernel<<<GRID_A, NTHREADS>>>(feat, w_gate, b_gate, seg);
    gap_finalize_alpha_kernel<<<B_SEGS, 256>>>(readout, alpha);
}